// round 1
// baseline (speedup 1.0000x reference)
#include <cuda_runtime.h>
#include <cstdint>

#define NB      8192
#define MDIM    32
#define NDIM    16
#define MAXIT   100
#define TOLF    1e-2f
#define ALPHAF  0.5f

// ---- static device scratch (allowed; no dynamic allocation anywhere) ----
__device__ float g_K    [NB * NDIM * NDIM];                 // 8 MB
__device__ float g_T1   [NB * NDIM * NDIM];                 // 8 MB
__device__ float g_zhist[(size_t)NB * MAXIT * 64];          // ~210 MB
__device__ int   g_flags[MAXIT + 1];
__device__ int   g_J;

// -------------------------------------------------------------------------
__global__ void init_flags_kernel() {
    int t = threadIdx.x;
    if (t <= MAXIT) g_flags[t] = 0;
}

// -------------------------------------------------------------------------
// Per-batch precompute: K = (0.5 I + A^T A)^{-1}  (16x16),  T1 = I - (A^T A) K.
// One warp per batch, 4 warps per block.
__global__ void __launch_bounds__(128) precompute_kernel(const float* __restrict__ A_g) {
    __shared__ __align__(16) float A_sh [4][MDIM * NDIM];
    __shared__ __align__(16) float F_sh [4][NDIM * NDIM];
    __shared__ float aug_sh[4][NDIM * 33];
    __shared__ float f_sh  [4][NDIM];

    const int lane  = threadIdx.x & 31;
    const int w     = threadIdx.x >> 5;
    const int batch = blockIdx.x * 4 + w;

    // load A (row-major 32x16), lane l loads row l (4x float4)
    const float4* Ab4 = reinterpret_cast<const float4*>(A_g + (size_t)batch * MDIM * NDIM);
    float4* As4 = reinterpret_cast<float4*>(A_sh[w]);
#pragma unroll
    for (int j = 0; j < 4; j++) As4[lane * 4 + j] = Ab4[lane * 4 + j];
    __syncwarp();

    // F = A^T A  (16x16); lanes 0..15 compute row i = lane
    if (lane < NDIM) {
        float acc[16];
#pragma unroll
        for (int j = 0; j < 16; j++) acc[j] = 0.f;
#pragma unroll 4
        for (int k = 0; k < MDIM; k++) {
            float aki = A_sh[w][k * NDIM + lane];
            const float4* row = reinterpret_cast<const float4*>(&A_sh[w][k * NDIM]);
            float4 r0 = row[0], r1 = row[1], r2 = row[2], r3 = row[3];
            acc[0]  += aki * r0.x;  acc[1]  += aki * r0.y;
            acc[2]  += aki * r0.z;  acc[3]  += aki * r0.w;
            acc[4]  += aki * r1.x;  acc[5]  += aki * r1.y;
            acc[6]  += aki * r1.z;  acc[7]  += aki * r1.w;
            acc[8]  += aki * r2.x;  acc[9]  += aki * r2.y;
            acc[10] += aki * r2.z;  acc[11] += aki * r2.w;
            acc[12] += aki * r3.x;  acc[13] += aki * r3.y;
            acc[14] += aki * r3.z;  acc[15] += aki * r3.w;
        }
#pragma unroll
        for (int j = 0; j < 16; j++) F_sh[w][lane * 16 + j] = acc[j];
    }
    __syncwarp();

    // augmented [F + 0.5 I | I] : 16 rows x 32 cols (row stride 33). lane owns column `lane`.
#pragma unroll
    for (int r = 0; r < NDIM; r++) {
        float v;
        if (lane < 16) v = F_sh[w][r * 16 + lane] + ((r == lane) ? 0.5f : 0.f);
        else           v = ((lane - 16) == r) ? 1.f : 0.f;
        aug_sh[w][r * 33 + lane] = v;
    }
    __syncwarp();

    // Gauss-Jordan, no pivoting (SPD, diag >= 0.5)
#pragma unroll 1
    for (int p = 0; p < NDIM; p++) {
        float piv = 1.0f / aug_sh[w][p * 33 + p];
        if (lane < NDIM) f_sh[w][lane] = aug_sh[w][lane * 33 + p];
        __syncwarp();
        float prow = aug_sh[w][p * 33 + lane] * piv;
        aug_sh[w][p * 33 + lane] = prow;
#pragma unroll
        for (int r = 0; r < NDIM; r++) {
            if (r != p) aug_sh[w][r * 33 + lane] -= f_sh[w][r] * prow;
        }
        __syncwarp();
    }

    // K = right half of aug; T1 = I - F*K. Store both (row-major 16x16).
#pragma unroll
    for (int e = 0; e < 8; e++) {
        int idx = e * 32 + lane;
        int i = idx >> 4, j = idx & 15;
        float kv = aug_sh[w][i * 33 + 16 + j];
        g_K[(size_t)batch * 256 + idx] = kv;
        float s = (i == j) ? 1.f : 0.f;
#pragma unroll
        for (int m = 0; m < 16; m++)
            s -= F_sh[w][i * 16 + m] * aug_sh[w][m * 33 + 16 + j];
        g_T1[(size_t)batch * 256 + idx] = s;
    }
}

// -------------------------------------------------------------------------
__device__ __forceinline__ float dot4(float4 a, float4 b) {
    return a.x * b.x + a.y * b.y + a.z * b.z + a.w * b.w;
}

// One warp per batch. Runs all 100 T-steps, records z_k history + per-k
// "any residual >= TOL" flags.
__global__ void __launch_bounds__(128) iterate_kernel(
        const float* __restrict__ u_g,
        const float* __restrict__ A_g,
        const float* __restrict__ b_g) {
    __shared__ __align__(16) float q_sh [4][16];
    __shared__ __align__(16) float r_sh [4][32];
    __shared__ __align__(16) float h_sh [4][16];
    __shared__ __align__(16) float g2_sh[4][16];
    __shared__ __align__(16) float t_sh [4][16];

    const int lane  = threadIdx.x & 31;
    const int w     = threadIdx.x >> 5;
    const int batch = blockIdx.x * 4 + w;
    const int i16   = lane & 15;
    const int half  = lane >> 4;               // 0 or 1
    const float sgn = half ? -1.f : 1.f;
    const int kbase = half * 16;

    const float* Ab = A_g + (size_t)batch * 512;

    // A row `lane`:
    float4 ar[4];
#pragma unroll
    for (int j = 0; j < 4; j++) ar[j] = reinterpret_cast<const float4*>(Ab)[lane * 4 + j];

    // A^T half column: at[kk] = A[kbase+kk][i16]
    float at[16];
#pragma unroll
    for (int kk = 0; kk < 16; kk++) at[kk] = Ab[(kbase + kk) * 16 + i16];

    // M row: K row i16 (lanes<16) or T1 row i16 (lanes>=16)
    const float* Mb = (half ? g_T1 : g_K) + (size_t)batch * 256 + i16 * 16;
    float4 mr[4];
#pragma unroll
    for (int j = 0; j < 4; j++) mr[j] = reinterpret_cast<const float4*>(Mb)[j];

    const float u_lo = u_g[batch * 16 + i16];
    const float bl   = b_g[batch * 32 + lane];

    float z_a = 0.f, z_b = 0.f;

#pragma unroll 1
    for (int k = 1; k <= MAXIT; k++) {
        float x_a = fmaxf(z_a, 0.f);
        float x_b = fmaxf(z_b, 0.f);
        float xa_o = __shfl_xor_sync(0xffffffffu, x_a, 16);
        float za_o = __shfl_xor_sync(0xffffffffu, z_a, 16);
        float pdiff = x_a - xa_o;                 // lane<16: x1-x2 ; lane>=16: -(x1-x2)

        // q = (2-2a)p - (z1 - z2) + 2a*u   (alpha = 0.5 -> coefficients 1, 1)
        if (lane < 16) q_sh[w][lane] = pdiff - (z_a - za_o) + u_lo;
        __syncwarp();

        // r_l = 2*x3 - z3 - b + (A q)_l
        const float4* qv = reinterpret_cast<const float4*>(&q_sh[w][0]);
        float4 q0 = qv[0], q1 = qv[1], q2 = qv[2], q3 = qv[3];
        float r = 2.f * x_b - z_b - bl;
        r += dot4(ar[0], q0) + dot4(ar[1], q1) + dot4(ar[2], q2) + dot4(ar[3], q3);
        r_sh[w][lane] = r;
        __syncwarp();

        // h = A^T r  (each half-warp sums half the k range, combine by xor-16)
        const float4* rv = reinterpret_cast<const float4*>(&r_sh[w][kbase]);
        float4 r0 = rv[0], r1 = rv[1], r2 = rv[2], r3 = rv[3];
        float hp = at[0]  * r0.x + at[1]  * r0.y + at[2]  * r0.z + at[3]  * r0.w
                 + at[4]  * r1.x + at[5]  * r1.y + at[6]  * r1.z + at[7]  * r1.w
                 + at[8]  * r2.x + at[9]  * r2.y + at[10] * r2.z + at[11] * r2.w
                 + at[12] * r3.x + at[13] * r3.y + at[14] * r3.z + at[15] * r3.w;
        hp += __shfl_xor_sync(0xffffffffu, hp, 16);
        if (lane < 16) h_sh[w][lane] = hp;
        __syncwarp();

        // lanes<16: g2 = K h ; lanes>=16: t = T1 h   (in parallel)
        const float4* hv = reinterpret_cast<const float4*>(&h_sh[w][0]);
        float4 h0 = hv[0], h1 = hv[1], h2 = hv[2], h3 = hv[3];
        float val = dot4(mr[0], h0) + dot4(mr[1], h1) + dot4(mr[2], h2) + dot4(mr[3], h3);
        if (lane < 16) g2_sh[w][lane] = val;
        else           t_sh[w][i16]  = val;
        __syncwarp();

        // w_l = r_l - (A g2)_l
        const float4* gv = reinterpret_cast<const float4*>(&g2_sh[w][0]);
        float4 g0 = gv[0], g1 = gv[1], g2v = gv[2], g3 = gv[3];
        float wv = r - (dot4(ar[0], g0) + dot4(ar[1], g1) + dot4(ar[2], g2v) + dot4(ar[3], g3));
        float tval = t_sh[w][i16];

        // updates: z1' = x1 - a*d - t ; z2' = x2 + a*d + t ; z3' = x3 - w
        float grad_a = pdiff - sgn * u_lo;        // = sgn * d
        float zan = x_a - ALPHAF * grad_a - sgn * tval;
        float zbn = x_b - wv;

        float res = fmaxf(fabsf(zan - z_a), fabsf(zbn - z_b));
        unsigned above = __any_sync(0xffffffffu, res >= TOLF);
        if (above && lane == 0 && k < MAXIT) g_flags[k] = 1;

        size_t base = ((size_t)(k - 1) * NB + batch) * 64;
        g_zhist[base + lane]      = zan;
        g_zhist[base + 32 + lane] = zbn;

        z_a = zan; z_b = zbn;
    }
}

// -------------------------------------------------------------------------
// J = number of while-loop steps the reference performs:
//   first k in [1,99] with all batch residuals < TOL, else 99.
__global__ void select_kernel() {
    int J = MAXIT - 1;
    for (int k = 1; k <= MAXIT - 1; k++) {
        if (g_flags[k] == 0) { J = k; break; }
    }
    g_J = J;
}

// z_star = z_{J+1} (history slot J). out = [u_star (8192x16), z_star (8192x64)].
__global__ void output_kernel(float* __restrict__ out) {
    int J = g_J;
    int idx = blockIdx.x * blockDim.x + threadIdx.x;
    if (idx >= NB * 64) return;
    int b = idx >> 6;
    int j = idx & 63;
    size_t base = ((size_t)J * NB + b) * 64;
    float z = g_zhist[base + j];
    out[NB * 16 + idx] = z;
    if (j < 16) {
        float z2 = g_zhist[base + 16 + j];
        out[b * 16 + j] = z - z2;     // u = z1 - z2
    }
}

// -------------------------------------------------------------------------
extern "C" void kernel_launch(void* const* d_in, const int* in_sizes, int n_in,
                              void* d_out, int out_size) {
    const float* u_nom = (const float*)d_in[0];
    const float* A     = (const float*)d_in[1];
    const float* b     = (const float*)d_in[2];
    float* out = (float*)d_out;

    init_flags_kernel<<<1, 128>>>();
    precompute_kernel<<<NB / 4, 128>>>(A);
    iterate_kernel<<<NB / 4, 128>>>(u_nom, A, b);
    select_kernel<<<1, 1>>>();
    output_kernel<<<(NB * 64 + 255) / 256, 256>>>(out);
}